// round 17
// baseline (speedup 1.0000x reference)
#include <cuda_runtime.h>

// 2x nearest-neighbor upsample — block-size sweep, final cell (1024 thr):
// in:  float32 [16, 64, 256, 256]  (1024 planes of 256x256)
// out: float32 [16, 64, 512, 512]
//
// Converged structure: thread indexing over OUTPUT quads.
//   idx -> (plane, h_in, ow4); input float2 index == idx (same linear index).
//   q = (x,x,y,y) stored to output rows 2h and 2h+1 at column ow4.
// Per warp: 1 x LDG.64 (256B contiguous) + 2 x STG.128 (512B contiguous).
// Measured: 256thr=193.1us, 512thr=191.9us (DRAM 84.4%); this probes 1024.
// All other axes closed (hints/MLP/STG.256/persistent all neutral or worse).

#define W_OUT4 128                  // float4 per output row (512/4)

__global__ void __launch_bounds__(1024) upsample2x_outidx_kernel(
    const float2* __restrict__ in2, float4* __restrict__ out4, int total)
{
    int idx = blockIdx.x * blockDim.x + threadIdx.x;
    if (idx >= total) return;

    // idx -> (plane, h, ow4); input float2 index == idx
    int ow4   = idx & (W_OUT4 - 1);         // 0..127
    int h     = (idx >> 7) & 255;           // 0..255
    int plane = idx >> 15;                  // 0..1023

    float2 v = in2[idx];
    float4 q = make_float4(v.x, v.x, v.y, v.y);

    // output row 2h of this plane, column ow4 (float4 units)
    long long base = ((long long)plane * 512 + 2 * h) * W_OUT4 + ow4;

    out4[base]          = q;   // row 2h
    out4[base + W_OUT4] = q;   // row 2h+1
}

extern "C" void kernel_launch(void* const* d_in, const int* in_sizes, int n_in,
                              void* d_out, int out_size)
{
    const float2* in2 = (const float2*)d_in[0];
    float4* out4 = (float4*)d_out;

    int total = in_sizes[0] / 2;            // 33,554,432 threads
    int threads = 1024;
    int blocks = (total + threads - 1) / threads;

    upsample2x_outidx_kernel<<<blocks, threads>>>(in2, out4, total);
}